// round 11
// baseline (speedup 1.0000x reference)
#include <cuda_runtime.h>
#include <cuda_device_runtime_api.h>

// Fused confusion-matrix reduction.
//   y_pred, y_true: [16, 3, 512, 512] f32 -> out [B*C, 4] = [tp, tn, fp, fn]
// tp = sum(p*t); fp = sum(p) - tp; fn = sum(t) - tp; tn = N - sum(p) - sum(t) + tp.
//
// Kernel 1: streaming reduce. 384 fat CTAs (vs 1536 thin ones) to collapse
// the cross-CTA L1tex-queue completion spread (B300: spr ~ 1.1 + 25*(oe*MLP-16)/T_CTA);
// load bursts capped at 8 LDG.128 via a non-unrolled outer loop.
// Kernel 2: tiny finalize, PDL-launched so its startup overlaps kernel 1.

#define SLICES 48                       // B*C
#define N_PER_SLICE (512 * 512)         // 262144 elements per slice
#define BLOCKS_PER_SLICE 8
#define THREADS 256
#define NBLOCKS (SLICES * BLOCKS_PER_SLICE)                       // 384
#define VECS_PER_BLOCK (N_PER_SLICE / BLOCKS_PER_SLICE / 4)       // 8192 float4
#define VECS_PER_THREAD (VECS_PER_BLOCK / THREADS)                // 32
#define OUTER 8
#define INNER 4                          // 4 p-vecs + 4 t-vecs per burst

// Per-block partials: [block][3] = {sum_p, sum_t, sum_pt}.
// Every slot overwritten each launch -> deterministic, graph-replay safe.
__device__ float g_part[NBLOCKS * 3];

__global__ __launch_bounds__(THREADS)
void cm_reduce_kernel(const float4* __restrict__ p4, const float4* __restrict__ t4) {
    const int blk = blockIdx.x;                         // 0 .. 383
    const long base = (long)blk * VECS_PER_BLOCK + threadIdx.x;

    float sp = 0.0f, st = 0.0f, spt = 0.0f;

#pragma unroll 1
    for (int i = 0; i < OUTER; i++) {
        float4 pv[INNER], tv[INNER];
#pragma unroll
        for (int j = 0; j < INNER; j++) {
            const long idx = base + (long)(i * INNER + j) * THREADS;
            pv[j] = __ldg(&p4[idx]);
            tv[j] = __ldg(&t4[idx]);
        }
#pragma unroll
        for (int j = 0; j < INNER; j++) {
            sp  += (pv[j].x + pv[j].y) + (pv[j].z + pv[j].w);
            st  += (tv[j].x + tv[j].y) + (tv[j].z + tv[j].w);
            spt += pv[j].x * tv[j].x + pv[j].y * tv[j].y
                 + pv[j].z * tv[j].z + pv[j].w * tv[j].w;
        }
    }

    // Intra-block tree reduction (warp shuffles + smem).
#pragma unroll
    for (int off = 16; off > 0; off >>= 1) {
        sp  += __shfl_down_sync(0xFFFFFFFFu, sp,  off);
        st  += __shfl_down_sync(0xFFFFFFFFu, st,  off);
        spt += __shfl_down_sync(0xFFFFFFFFu, spt, off);
    }

    __shared__ float sm[3][THREADS / 32];
    const int wid = threadIdx.x >> 5;
    const int lid = threadIdx.x & 31;
    if (lid == 0) {
        sm[0][wid] = sp;
        sm[1][wid] = st;
        sm[2][wid] = spt;
    }
    __syncthreads();

    if (threadIdx.x == 0) {
        float a = 0.0f, b = 0.0f, c = 0.0f;
#pragma unroll
        for (int w = 0; w < THREADS / 32; w++) {
            a += sm[0][w];
            b += sm[1][w];
            c += sm[2][w];
        }
        g_part[blk * 3 + 0] = a;
        g_part[blk * 3 + 1] = b;
        g_part[blk * 3 + 2] = c;
    }
}

// Finalize: 384 threads; 8 lanes per slice (one lane per per-slice block),
// 3-step sub-warp shuffle fold, double only for the final combine.
// PDL: starts alongside the reduce, blocks at the grid dependency sync.
#define FIN_THREADS (SLICES * BLOCKS_PER_SLICE)   // 384
__global__ __launch_bounds__(FIN_THREADS)
void cm_finalize_kernel(float* __restrict__ out) {
    cudaGridDependencySynchronize();

    const int tid = threadIdx.x;                  // 0 .. 383
    const int part = tid & 7;                     // block-within-slice
    const int s = tid >> 3;                       // slice 0 .. 47

    const int idx = (s * BLOCKS_PER_SLICE + part) * 3;
    float a = g_part[idx + 0];
    float b = g_part[idx + 1];
    float c = g_part[idx + 2];

#pragma unroll
    for (int off = 4; off > 0; off >>= 1) {
        a += __shfl_down_sync(0xFFFFFFFFu, a, off, 8);
        b += __shfl_down_sync(0xFFFFFFFFu, b, off, 8);
        c += __shfl_down_sync(0xFFFFFFFFu, c, off, 8);
    }

    if (part == 0) {
        const double da = a, db = b, dc = c;
        const double n = (double)N_PER_SLICE;
        out[s * 4 + 0] = (float)dc;                   // tp
        out[s * 4 + 1] = (float)(n - da - db + dc);   // tn
        out[s * 4 + 2] = (float)(da - dc);            // fp
        out[s * 4 + 3] = (float)(db - dc);            // fn
    }
}

extern "C" void kernel_launch(void* const* d_in, const int* in_sizes, int n_in,
                              void* d_out, int out_size) {
    const float4* p4 = (const float4*)d_in[0];   // y_pred
    const float4* t4 = (const float4*)d_in[1];   // y_true
    float* out = (float*)d_out;

    cm_reduce_kernel<<<NBLOCKS, THREADS>>>(p4, t4);

    // PDL launch of the finalize: overlap its launch latency with the reduce.
    cudaLaunchConfig_t cfg = {};
    cfg.gridDim = dim3(1, 1, 1);
    cfg.blockDim = dim3(FIN_THREADS, 1, 1);
    cfg.dynamicSmemBytes = 0;
    cfg.stream = 0;  // same (captured) default stream as the <<<>>> launch
    cudaLaunchAttribute attrs[1];
    attrs[0].id = cudaLaunchAttributeProgrammaticStreamSerialization;
    attrs[0].val.programmaticStreamSerializationAllowed = 1;
    cfg.attrs = attrs;
    cfg.numAttrs = 1;
    cudaLaunchKernelEx(&cfg, cm_finalize_kernel, out);
}

// round 12
// speedup vs baseline: 1.3888x; 1.3888x over previous
#include <cuda_runtime.h>
#include <cuda_device_runtime_api.h>

// Fused confusion-matrix reduction.
//   y_pred, y_true: [16, 3, 512, 512] f32 -> out [B*C, 4] = [tp, tn, fp, fn]
// tp = sum(p*t); fp = sum(p) - tp; fn = sum(t) - tp; tn = N - sum(p) - sum(t) + tp.
//
// Kernel 1: streaming reduce, 768 CTAs = 16 per slice. 768 < 1184 resident
// capacity (8 CTAs/SM x 148 SMs) -> the whole grid runs in ONE wave, no
// straggler wave (1536 blocks left a 352-block tail; 384 blocks starved MLP).
// Load bursts capped at 8 LDG.128 per iteration.
// Kernel 2: tiny finalize, PDL-launched so its startup overlaps kernel 1.

#define SLICES 48                       // B*C
#define N_PER_SLICE (512 * 512)         // 262144 elements per slice
#define BLOCKS_PER_SLICE 16
#define THREADS 256
#define NBLOCKS (SLICES * BLOCKS_PER_SLICE)                       // 768
#define VECS_PER_BLOCK (N_PER_SLICE / BLOCKS_PER_SLICE / 4)       // 4096 float4
#define VECS_PER_THREAD (VECS_PER_BLOCK / THREADS)                // 16
#define OUTER 4
#define INNER 4                          // 4 p-vecs + 4 t-vecs per burst

// Per-block partials: [block][3] = {sum_p, sum_t, sum_pt}.
// Every slot overwritten each launch -> deterministic, graph-replay safe.
__device__ float g_part[NBLOCKS * 3];

__global__ __launch_bounds__(THREADS)
void cm_reduce_kernel(const float4* __restrict__ p4, const float4* __restrict__ t4) {
    const int blk = blockIdx.x;                         // 0 .. 767
    const long base = (long)blk * VECS_PER_BLOCK + threadIdx.x;

    float sp = 0.0f, st = 0.0f, spt = 0.0f;

#pragma unroll 1
    for (int i = 0; i < OUTER; i++) {
        float4 pv[INNER], tv[INNER];
#pragma unroll
        for (int j = 0; j < INNER; j++) {
            const long idx = base + (long)(i * INNER + j) * THREADS;
            pv[j] = __ldg(&p4[idx]);
            tv[j] = __ldg(&t4[idx]);
        }
#pragma unroll
        for (int j = 0; j < INNER; j++) {
            sp  += (pv[j].x + pv[j].y) + (pv[j].z + pv[j].w);
            st  += (tv[j].x + tv[j].y) + (tv[j].z + tv[j].w);
            spt += pv[j].x * tv[j].x + pv[j].y * tv[j].y
                 + pv[j].z * tv[j].z + pv[j].w * tv[j].w;
        }
    }

    // Intra-block tree reduction (warp shuffles + smem).
#pragma unroll
    for (int off = 16; off > 0; off >>= 1) {
        sp  += __shfl_down_sync(0xFFFFFFFFu, sp,  off);
        st  += __shfl_down_sync(0xFFFFFFFFu, st,  off);
        spt += __shfl_down_sync(0xFFFFFFFFu, spt, off);
    }

    __shared__ float sm[3][THREADS / 32];
    const int wid = threadIdx.x >> 5;
    const int lid = threadIdx.x & 31;
    if (lid == 0) {
        sm[0][wid] = sp;
        sm[1][wid] = st;
        sm[2][wid] = spt;
    }
    __syncthreads();

    if (threadIdx.x == 0) {
        float a = 0.0f, b = 0.0f, c = 0.0f;
#pragma unroll
        for (int w = 0; w < THREADS / 32; w++) {
            a += sm[0][w];
            b += sm[1][w];
            c += sm[2][w];
        }
        g_part[blk * 3 + 0] = a;
        g_part[blk * 3 + 1] = b;
        g_part[blk * 3 + 2] = c;
    }
}

// Finalize: 768 threads; 16 lanes per slice (one per per-slice block),
// 4-step sub-warp shuffle fold, double only for the final combine.
// PDL: starts alongside the reduce, blocks at the grid dependency sync.
#define FIN_THREADS NBLOCKS   // 768
__global__ __launch_bounds__(FIN_THREADS)
void cm_finalize_kernel(float* __restrict__ out) {
    cudaGridDependencySynchronize();

    const int tid = threadIdx.x;                  // 0 .. 767
    const int part = tid & 15;                    // block-within-slice
    const int s = tid >> 4;                       // slice 0 .. 47

    const int idx = (s * BLOCKS_PER_SLICE + part) * 3;
    float a = g_part[idx + 0];
    float b = g_part[idx + 1];
    float c = g_part[idx + 2];

#pragma unroll
    for (int off = 8; off > 0; off >>= 1) {
        a += __shfl_down_sync(0xFFFFFFFFu, a, off, 16);
        b += __shfl_down_sync(0xFFFFFFFFu, b, off, 16);
        c += __shfl_down_sync(0xFFFFFFFFu, c, off, 16);
    }

    if (part == 0) {
        const double da = a, db = b, dc = c;
        const double n = (double)N_PER_SLICE;
        out[s * 4 + 0] = (float)dc;                   // tp
        out[s * 4 + 1] = (float)(n - da - db + dc);   // tn
        out[s * 4 + 2] = (float)(da - dc);            // fp
        out[s * 4 + 3] = (float)(db - dc);            // fn
    }
}

extern "C" void kernel_launch(void* const* d_in, const int* in_sizes, int n_in,
                              void* d_out, int out_size) {
    const float4* p4 = (const float4*)d_in[0];   // y_pred
    const float4* t4 = (const float4*)d_in[1];   // y_true
    float* out = (float*)d_out;

    cm_reduce_kernel<<<NBLOCKS, THREADS>>>(p4, t4);

    // PDL launch of the finalize: overlap its launch latency with the reduce.
    cudaLaunchConfig_t cfg = {};
    cfg.gridDim = dim3(1, 1, 1);
    cfg.blockDim = dim3(FIN_THREADS, 1, 1);
    cfg.dynamicSmemBytes = 0;
    cfg.stream = 0;  // same (captured) default stream as the <<<>>> launch
    cudaLaunchAttribute attrs[1];
    attrs[0].id = cudaLaunchAttributeProgrammaticStreamSerialization;
    attrs[0].val.programmaticStreamSerializationAllowed = 1;
    cfg.attrs = attrs;
    cfg.numAttrs = 1;
    cudaLaunchKernelEx(&cfg, cm_finalize_kernel, out);
}